// round 5
// baseline (speedup 1.0000x reference)
#include <cuda_runtime.h>

typedef unsigned long long u64;

#define N_POS   16384
#define CDIM    128
#define CTOT    512
#define BATCH   2
#define BH      8
#define SCALE   0.08838834764831845f

// Scratch (allocation-free): per-(b,h) kv matrices + k row-sums.
__device__ float g_kv[BH * CDIM * CDIM];
__device__ float g_ksum[BH * CDIM];

// ---------------- packed f32x2 helpers ----------------
__device__ __forceinline__ u64 pk2(float x, float y) {
    u64 r; asm("mov.b64 %0, {%1, %2};" : "=l"(r) : "f"(x), "f"(y)); return r;
}
__device__ __forceinline__ void fma2(u64 &d, u64 a, u64 b) {
    asm("fma.rn.f32x2 %0, %1, %2, %0;" : "+l"(d) : "l"(a), "l"(b));
}
__device__ __forceinline__ float2 up2(u64 v) {
    float2 f; asm("mov.b64 {%0, %1}, %2;" : "=f"(f.x), "=f"(f.y) : "l"(v)); return f;
}
__device__ __forceinline__ float softplus(float x) {
    // log1p(exp(x)) = max(x,0) + log(1 + exp(-|x|))
    return fmaxf(x, 0.0f) + __logf(1.0f + __expf(-fabsf(x)));
}

// 8x8 rank-1 update in packed f32x2: acc[i][p] += a[i] * (b[2p], b[2p+1])
__device__ __forceinline__ void rank1(u64 (&acc)[8][4],
                                      const float* __restrict__ ar,
                                      const float* __restrict__ br) {
    float4 a0 = *(const float4*)ar;
    float4 a1 = *(const float4*)(ar + 4);
    ulonglong2 b01 = *(const ulonglong2*)br;        // pairs already packed
    ulonglong2 b23 = *(const ulonglong2*)(br + 4);
    u64 bb[4] = { b01.x, b01.y, b23.x, b23.y };
    u64 ad[8];
    ad[0] = pk2(a0.x, a0.x); ad[1] = pk2(a0.y, a0.y);
    ad[2] = pk2(a0.z, a0.z); ad[3] = pk2(a0.w, a0.w);
    ad[4] = pk2(a1.x, a1.x); ad[5] = pk2(a1.y, a1.y);
    ad[6] = pk2(a1.z, a1.z); ad[7] = pk2(a1.w, a1.w);
#pragma unroll
    for (int i = 0; i < 8; i++)
#pragma unroll
        for (int p = 0; p < 4; p++)
            fma2(acc[i][p], ad[i], bb[p]);
}

// ---------------- zero scratch ----------------
__global__ void zero_kernel() {
    int i = blockIdx.x * blockDim.x + threadIdx.x;
    if (i < BH * CDIM * CDIM) g_kv[i]   = 0.0f;
    if (i < BH * CDIM)        g_ksum[i] = 0.0f;
}

// ---------------- pass 1: kv = softplus(K) @ V^T, ksum = softplus(K) @ 1 ----------------
#define P1_CHUNK 256
#define P1_STEPS 16
#define SKS 132   // padded transpose stride

__global__ __launch_bounds__(256, 2) void kv_kernel(const float* __restrict__ x) {
    __shared__ float sk[2][16][SKS];
    __shared__ float sv[2][16][SKS];
    __shared__ float ksum_s[CDIM];

    const int tid = threadIdx.x;
    const int bh  = blockIdx.y;
    const int b   = bh >> 2, h = bh & 3;
    const size_t S    = (size_t)BATCH * CTOT * N_POS;
    const size_t base = (size_t)(b * CTOT + h * CDIM) * N_POS + (size_t)blockIdx.x * P1_CHUNK;
    const float* kp = x + S + base;
    const float* vp = x + 2 * S + base;

    if (tid < CDIM) ksum_s[tid] = 0.0f;

    const int col4 = (tid & 3) * 4;     // n-offset within 16-wide k-step
    const int r0   = tid >> 2;          // rows r0 and r0+64
    const int tr8  = (tid >> 4) * 8;    // output c-tile
    const int tc8  = (tid & 15) * 8;    // output d-tile

    u64 acc[8][4];
#pragma unroll
    for (int i = 0; i < 8; i++)
#pragma unroll
        for (int p = 0; p < 4; p++) acc[i][p] = 0ULL;

    float ks0 = 0.0f, ks1 = 0.0f;

    float4 kr0 = *(const float4*)(kp + (size_t)r0 * N_POS + col4);
    float4 kr1 = *(const float4*)(kp + (size_t)(r0 + 64) * N_POS + col4);
    float4 vr0 = *(const float4*)(vp + (size_t)r0 * N_POS + col4);
    float4 vr1 = *(const float4*)(vp + (size_t)(r0 + 64) * N_POS + col4);

    for (int s = 0; s < P1_STEPS; s++) {
        const int buf = s & 1;
        {
            float t0 = softplus(kr0.x), t1 = softplus(kr0.y),
                  t2 = softplus(kr0.z), t3 = softplus(kr0.w);
            ks0 += (t0 + t1) + (t2 + t3);
            sk[buf][col4 + 0][r0] = t0; sk[buf][col4 + 1][r0] = t1;
            sk[buf][col4 + 2][r0] = t2; sk[buf][col4 + 3][r0] = t3;
            t0 = softplus(kr1.x); t1 = softplus(kr1.y);
            t2 = softplus(kr1.z); t3 = softplus(kr1.w);
            ks1 += (t0 + t1) + (t2 + t3);
            sk[buf][col4 + 0][r0 + 64] = t0; sk[buf][col4 + 1][r0 + 64] = t1;
            sk[buf][col4 + 2][r0 + 64] = t2; sk[buf][col4 + 3][r0 + 64] = t3;
            sv[buf][col4 + 0][r0] = vr0.x; sv[buf][col4 + 1][r0] = vr0.y;
            sv[buf][col4 + 2][r0] = vr0.z; sv[buf][col4 + 3][r0] = vr0.w;
            sv[buf][col4 + 0][r0 + 64] = vr1.x; sv[buf][col4 + 1][r0 + 64] = vr1.y;
            sv[buf][col4 + 2][r0 + 64] = vr1.z; sv[buf][col4 + 3][r0 + 64] = vr1.w;
        }
        __syncthreads();
        if (s + 1 < P1_STEPS) {
            const size_t off = (size_t)(s + 1) * 16 + col4;
            kr0 = *(const float4*)(kp + (size_t)r0 * N_POS + off);
            kr1 = *(const float4*)(kp + (size_t)(r0 + 64) * N_POS + off);
            vr0 = *(const float4*)(vp + (size_t)r0 * N_POS + off);
            vr1 = *(const float4*)(vp + (size_t)(r0 + 64) * N_POS + off);
        }
#pragma unroll
        for (int kk = 0; kk < 16; kk++)
            rank1(acc, &sk[buf][kk][tr8], &sv[buf][kk][tc8]);
    }

    atomicAdd(&ksum_s[r0],      ks0);
    atomicAdd(&ksum_s[r0 + 64], ks1);
    __syncthreads();
    if (tid < CDIM) atomicAdd(&g_ksum[bh * CDIM + tid], ksum_s[tid]);

    float* kvb = g_kv + bh * CDIM * CDIM;
#pragma unroll
    for (int i = 0; i < 8; i++) {
        float* row = kvb + (tr8 + i) * CDIM + tc8;
#pragma unroll
        for (int p = 0; p < 4; p++) {
            float2 v = up2(acc[i][p]);
            atomicAdd(row + 2 * p,     v.x);
            atomicAdd(row + 2 * p + 1, v.y);
        }
    }
}

// ---------------- pass 2: out[d,n] = scale*zinv[n] * sum_c softplus(q)[c,n]*kv[c,d] ----------------
#define P2_SMEM_FLOATS 21760   // skv 16384 + qs 4096 + zred 1024 + zinv 128 + ksum 128

__global__ __launch_bounds__(256, 2) void out_kernel(const float* __restrict__ x,
                                                     float* __restrict__ out) {
    extern __shared__ float sm[];
    float* skv  = sm;            // [128][128]
    float* qs   = sm + 16384;    // [2][16][128]
    float* zred = sm + 20480;    // [8][128]
    float* zinv = sm + 21504;    // [128]
    float* ksm  = sm + 21632;    // [128]

    const int tid = threadIdx.x;
    const int bh  = blockIdx.y;
    const int b   = bh >> 2, h = bh & 3;
    const size_t rowbase = (size_t)(b * CTOT + h * CDIM) * N_POS + (size_t)blockIdx.x * 128;
    const float* qp = x + rowbase;          // q = x[0]
    float* op = out + rowbase;

    {   // cache full kv[bh] (mostly L2 hits: 128 blocks share it)
        const float4* src = (const float4*)(g_kv + bh * CDIM * CDIM);
        float4* dst = (float4*)skv;
#pragma unroll
        for (int i = 0; i < 16; i++) dst[tid + i * 256] = src[tid + i * 256];
    }
    if (tid < CDIM) ksm[tid] = g_ksum[bh * CDIM + tid];

    const int n4   = (tid & 31) * 4;    // fixed n-columns per thread (load/z)
    const int crow = tid >> 5;          // 0..7
    const int tr8  = (tid >> 4) * 8;    // output d-tile
    const int tc8  = (tid & 15) * 8;    // output n-tile

    u64 acc[8][4];
#pragma unroll
    for (int i = 0; i < 8; i++)
#pragma unroll
        for (int p = 0; p < 4; p++) acc[i][p] = 0ULL;
    float z0 = 0.f, z1 = 0.f, z2 = 0.f, z3 = 0.f;

    float4 qr0 = *(const float4*)(qp + (size_t)crow * N_POS + n4);
    float4 qr1 = *(const float4*)(qp + (size_t)(crow + 8) * N_POS + n4);

    __syncthreads();

    for (int s = 0; s < 8; s++) {
        const int buf = s & 1;
        float* qb = qs + buf * 2048;
        {
            float t0 = softplus(qr0.x), t1 = softplus(qr0.y),
                  t2 = softplus(qr0.z), t3 = softplus(qr0.w);
            float kw = ksm[s * 16 + crow];
            z0 += t0 * kw; z1 += t1 * kw; z2 += t2 * kw; z3 += t3 * kw;
            *(float4*)(qb + crow * 128 + n4) = make_float4(t0, t1, t2, t3);
            t0 = softplus(qr1.x); t1 = softplus(qr1.y);
            t2 = softplus(qr1.z); t3 = softplus(qr1.w);
            kw = ksm[s * 16 + crow + 8];
            z0 += t0 * kw; z1 += t1 * kw; z2 += t2 * kw; z3 += t3 * kw;
            *(float4*)(qb + (crow + 8) * 128 + n4) = make_float4(t0, t1, t2, t3);
        }
        __syncthreads();
        if (s < 7) {
            const float* qn = qp + (size_t)(s + 1) * 16 * N_POS;
            qr0 = *(const float4*)(qn + (size_t)crow * N_POS + n4);
            qr1 = *(const float4*)(qn + (size_t)(crow + 8) * N_POS + n4);
        }
#pragma unroll
        for (int kk = 0; kk < 16; kk++)
            rank1(acc, &skv[(s * 16 + kk) * CDIM + tr8], qb + kk * 128 + tc8);
    }

    // z reduction: 8 partials per n column
    *(float4*)(zred + crow * 128 + n4) = make_float4(z0, z1, z2, z3);
    __syncthreads();
    if (tid < 128) {
        float zs = 0.0f;
#pragma unroll
        for (int r = 0; r < 8; r++) zs += zred[r * 128 + tid];
        zinv[tid] = SCALE / (zs * SCALE + (float)N_POS);  // folds out-scale
    }
    __syncthreads();

    float zv[8];
#pragma unroll
    for (int j = 0; j < 8; j++) zv[j] = zinv[tc8 + j];
#pragma unroll
    for (int i = 0; i < 8; i++) {
        float* row = op + (size_t)(tr8 + i) * N_POS + tc8;
        float o[8];
#pragma unroll
        for (int p = 0; p < 4; p++) {
            float2 v = up2(acc[i][p]);
            o[2 * p]     = v.x * zv[2 * p];
            o[2 * p + 1] = v.y * zv[2 * p + 1];
        }
        *(float4*)(row)     = make_float4(o[0], o[1], o[2], o[3]);
        *(float4*)(row + 4) = make_float4(o[4], o[5], o[6], o[7]);
    }
}

// ---------------- launch ----------------
extern "C" void kernel_launch(void* const* d_in, const int* in_sizes, int n_in,
                              void* d_out, int out_size) {
    (void)in_sizes; (void)n_in; (void)out_size;
    const float* x = (const float*)d_in[0];
    float* out = (float*)d_out;

    cudaFuncSetAttribute(out_kernel, cudaFuncAttributeMaxDynamicSharedMemorySize,
                         P2_SMEM_FLOATS * (int)sizeof(float));

    zero_kernel<<<(BH * CDIM * CDIM + 255) / 256, 256>>>();
    kv_kernel<<<dim3(64, BH), 256>>>(x);
    out_kernel<<<dim3(128, BH), 256, P2_SMEM_FLOATS * sizeof(float)>>>(x, out);
}